// round 1
// baseline (speedup 1.0000x reference)
#include <cuda_runtime.h>
#include <stdint.h>

#define NN 20000
#define NE 320000

// ---------------- static scratch (no allocations allowed) ----------------
__device__ float g_bufA[(size_t)NN * 1024];
__device__ float g_bufB[(size_t)NN * 1024];
__device__ float g_bufC[(size_t)NN * 1024];
__device__ float g_cnt[NN];
__device__ float g_inv[NN];
__device__ int   g_idx64;

// ---------------- helpers ----------------
__device__ __forceinline__ int get_idx(const void* e, long long i) {
    if (g_idx64) return (int)((const long long*)e)[i];
    return ((const int*)e)[i];
}

// Detect whether edge_index is int64 (little-endian: odd int32 words are 0)
__global__ void detect_idx_kernel(const int* e) {
    if (threadIdx.x == 0 && blockIdx.x == 0) {
        int is64 = 1;
        for (int k = 0; k < 128; k++) {
            if (e[2 * k + 1] != 0) { is64 = 0; break; }
        }
        g_idx64 = is64;
    }
}

__global__ void zero_kernel(float* p, int n) {
    int i = blockIdx.x * blockDim.x + threadIdx.x;
    if (i < n) p[i] = 0.f;
}

__global__ void count_deg_kernel(const void* eidx) {
    int i = blockIdx.x * blockDim.x + threadIdx.x;
    if (i < NE) {
        int dst = get_idx(eidx, (long long)NE + i);
        atomicAdd(&g_cnt[dst], 1.f);
    }
}

__global__ void make_inv_kernel() {
    int i = blockIdx.x * blockDim.x + threadIdx.x;
    if (i < NN) {
        float c = g_cnt[i];
        g_inv[i] = (c > 0.f) ? (1.f / c) : 0.f;
    }
}

// ---------------- SGEMM: C = act( rowscale[r] * (A@B) + bias ) ----------------
// A: MxK row-major, B: KxN row-major. 128x128 tile, BK=8, 256 threads, 8x8/thread.
// rowscale==nullptr -> scale 1; rowscale[r]==0 -> output forced to 0 (isolated-node mask).
__global__ void __launch_bounds__(256, 2)
sgemm_kernel(const float* __restrict__ A, const float* __restrict__ B,
             const float* __restrict__ bias, const float* __restrict__ rowscale,
             float* __restrict__ C, int M, int N, int K, int doRelu)
{
    __shared__ float As[8][128];
    __shared__ float Bs[8][128];

    const int tid = threadIdx.x;
    const int rowBase = blockIdx.y * 128;
    const int colBase = blockIdx.x * 128;

    // A-tile load map: 128 rows x 8 cols, one float4 per thread
    const int ar = tid >> 1;
    const int ak = (tid & 1) * 4;
    // B-tile load map: 8 rows x 128 cols, one float4 per thread
    const int bk = tid >> 5;
    const int bc = (tid & 31) * 4;

    const int tx = tid & 15;   // N direction
    const int ty = tid >> 4;   // M direction

    float acc[8][8];
#pragma unroll
    for (int i = 0; i < 8; i++)
#pragma unroll
        for (int j = 0; j < 8; j++) acc[i][j] = 0.f;

    for (int k0 = 0; k0 < K; k0 += 8) {
        float4 av = make_float4(0.f, 0.f, 0.f, 0.f);
        const int arow = rowBase + ar;
        if (arow < M && (k0 + ak) < K)
            av = *(const float4*)(A + (size_t)arow * K + k0 + ak);
        As[ak + 0][ar] = av.x;
        As[ak + 1][ar] = av.y;
        As[ak + 2][ar] = av.z;
        As[ak + 3][ar] = av.w;

        float4 bv = make_float4(0.f, 0.f, 0.f, 0.f);
        const int brow = k0 + bk;
        const int bcol = colBase + bc;
        if (brow < K && bcol < N)
            bv = *(const float4*)(B + (size_t)brow * N + bcol);
        *(float4*)&Bs[bk][bc] = bv;

        __syncthreads();

#pragma unroll
        for (int k = 0; k < 8; k++) {
            float ra[8], rb[8];
#pragma unroll
            for (int i = 0; i < 8; i++) ra[i] = As[k][ty * 8 + i];
#pragma unroll
            for (int j = 0; j < 8; j++) rb[j] = Bs[k][tx * 8 + j];
#pragma unroll
            for (int i = 0; i < 8; i++)
#pragma unroll
                for (int j = 0; j < 8; j++)
                    acc[i][j] = fmaf(ra[i], rb[j], acc[i][j]);
        }
        __syncthreads();
    }

#pragma unroll
    for (int i = 0; i < 8; i++) {
        const int r = rowBase + ty * 8 + i;
        if (r >= M) continue;
        const float rs = rowscale ? rowscale[r] : 1.f;
        const bool masked = (rowscale != nullptr) && (rs == 0.f);
#pragma unroll
        for (int j = 0; j < 8; j++) {
            const int c = colBase + tx * 8 + j;
            if (c >= N) continue;
            float v = acc[i][j] * rs + bias[c];
            if (doRelu) v = fmaxf(v, 0.f);
            if (masked) v = 0.f;
            C[(size_t)r * N + c] = v;
        }
    }
}

// ---------------- edge scatter ----------------
// For each edge e and column c: r = relu(t[src][c] + dx*wpos[0][c] + dy*wpos[1][c]);
// atomicAdd(s[dst][c], r).  H = 4 << laneShift.
__global__ void edge_scatter_kernel(const float* __restrict__ t,
                                    const float* __restrict__ pos,
                                    const void* __restrict__ eidx,
                                    const float* __restrict__ wpos,
                                    float* __restrict__ s, int laneShift)
{
    const long long gid = (long long)blockIdx.x * blockDim.x + threadIdx.x;
    const int lanes = 1 << laneShift;
    const int H = lanes * 4;
    const long long e = gid >> laneShift;
    if (e >= NE) return;
    const int c4 = (int)(gid & (lanes - 1)) << 2;

    const int src = get_idx(eidx, e);
    const int dst = get_idx(eidx, (long long)NE + e);

    const float dx = pos[2 * src] - pos[2 * dst];
    const float dy = pos[2 * src + 1] - pos[2 * dst + 1];

    const float4 tv = *(const float4*)(t + (size_t)src * H + c4);
    const float4 wx = *(const float4*)(wpos + c4);
    const float4 wy = *(const float4*)(wpos + H + c4);

    float4 r;
    r.x = fmaxf(fmaf(dx, wx.x, fmaf(dy, wy.x, tv.x)), 0.f);
    r.y = fmaxf(fmaf(dx, wx.y, fmaf(dy, wy.y, tv.y)), 0.f);
    r.z = fmaxf(fmaf(dx, wx.z, fmaf(dy, wy.z, tv.z)), 0.f);
    r.w = fmaxf(fmaf(dx, wx.w, fmaf(dy, wy.w, tv.w)), 0.f);

    float* sp = s + (size_t)dst * H + c4;
    atomicAdd(sp + 0, r.x);
    atomicAdd(sp + 1, r.y);
    atomicAdd(sp + 2, r.z);
    atomicAdd(sp + 3, r.w);
}

// ---------------- host-side helpers ----------------
static inline void run_sgemm(const float* A, const float* B, const float* bias,
                             const float* rowscale, float* C,
                             int M, int N, int K, int doRelu)
{
    dim3 grid((N + 127) / 128, (M + 127) / 128);
    sgemm_kernel<<<grid, 256>>>(A, B, bias, rowscale, C, M, N, K, doRelu);
}

static inline void run_zero(float* p, long long n)
{
    zero_kernel<<<(unsigned)((n + 255) / 256), 256>>>(p, (int)n);
}

static inline void run_edge(const float* t, const float* pos, const void* eidx,
                            const float* wpos, float* s, int laneShift)
{
    const long long total = (long long)NE << laneShift;
    edge_scatter_kernel<<<(unsigned)((total + 255) / 256), 256>>>(t, pos, eidx, wpos, s, laneShift);
}

extern "C" void kernel_launch(void* const* d_in, const int* in_sizes, int n_in,
                              void* d_out, int out_size)
{
    const float* h    = (const float*)d_in[0];
    const float* pos  = (const float*)d_in[1];
    const void*  eidx = d_in[2];

    const float* l1_w1 = (const float*)d_in[3];
    const float* l1_b1 = (const float*)d_in[4];
    const float* l1_w2 = (const float*)d_in[5];
    const float* l1_b2 = (const float*)d_in[6];
    const float* l2_w1 = (const float*)d_in[7];
    const float* l2_b1 = (const float*)d_in[8];
    const float* l2_w2 = (const float*)d_in[9];
    const float* l2_b2 = (const float*)d_in[10];
    const float* l3_w1 = (const float*)d_in[11];
    const float* l3_b1 = (const float*)d_in[12];
    const float* l3_w2 = (const float*)d_in[13];
    const float* l3_b2 = (const float*)d_in[14];
    const float* l4_w1 = (const float*)d_in[15];
    const float* l4_b1 = (const float*)d_in[16];
    const float* l4_w2 = (const float*)d_in[17];
    const float* l4_b2 = (const float*)d_in[18];
    const float* hd_w1 = (const float*)d_in[19];
    const float* hd_b1 = (const float*)d_in[20];
    const float* hd_w2 = (const float*)d_in[21];
    const float* hd_b2 = (const float*)d_in[22];
    const float* hd_w3 = (const float*)d_in[23];
    const float* hd_b3 = (const float*)d_in[24];

    float *bufA, *bufB, *bufC, *cnt, *inv;
    cudaGetSymbolAddress((void**)&bufA, g_bufA);
    cudaGetSymbolAddress((void**)&bufB, g_bufB);
    cudaGetSymbolAddress((void**)&bufC, g_bufC);
    cudaGetSymbolAddress((void**)&cnt, g_cnt);
    cudaGetSymbolAddress((void**)&inv, g_inv);

    // --- setup: index dtype detection + in-degree counts ---
    detect_idx_kernel<<<1, 32>>>((const int*)d_in[2]);
    run_zero(cnt, NN);
    count_deg_kernel<<<(NE + 255) / 256, 256>>>(eidx);
    make_inv_kernel<<<(NN + 255) / 256, 256>>>();

    // --- layer 1: 16 -> 128 -> 128 ---
    run_sgemm(h, l1_w1, l1_b1, nullptr, bufB, NN, 128, 16, 0);        // t = h@w1f + b1
    run_zero(bufC, (long long)NN * 128);
    run_edge(bufB, pos, eidx, l1_w1 + (size_t)16 * 128, bufC, 5);     // s = sum relu(...)
    run_sgemm(bufC, l1_w2, l1_b2, inv, bufA, NN, 128, 128, 1);        // h1 = relu(mean@w2+b2)

    // --- layer 2: 128 -> 256 -> 256 ---
    run_sgemm(bufA, l2_w1, l2_b1, nullptr, bufB, NN, 256, 128, 0);
    run_zero(bufC, (long long)NN * 256);
    run_edge(bufB, pos, eidx, l2_w1 + (size_t)128 * 256, bufC, 6);
    run_sgemm(bufC, l2_w2, l2_b2, inv, bufA, NN, 256, 256, 1);

    // --- layer 3: 256 -> 1024 -> 1024 ---
    run_sgemm(bufA, l3_w1, l3_b1, nullptr, bufB, NN, 1024, 256, 0);
    run_zero(bufC, (long long)NN * 1024);
    run_edge(bufB, pos, eidx, l3_w1 + (size_t)256 * 1024, bufC, 8);
    run_sgemm(bufC, l3_w2, l3_b2, inv, bufA, NN, 1024, 1024, 1);

    // --- layer 4: 1024 -> 1024 -> 1024 ---
    run_sgemm(bufA, l4_w1, l4_b1, nullptr, bufB, NN, 1024, 1024, 0);
    run_zero(bufC, (long long)NN * 1024);
    run_edge(bufB, pos, eidx, l4_w1 + (size_t)1024 * 1024, bufC, 8);
    run_sgemm(bufC, l4_w2, l4_b2, inv, bufA, NN, 1024, 1024, 1);

    // --- head MLP ---
    run_sgemm(bufA, hd_w1, hd_b1, nullptr, bufB, NN, 1024, 1024, 1);
    run_sgemm(bufB, hd_w2, hd_b2, nullptr, bufC, NN, 512, 1024, 1);
    run_sgemm(bufC, hd_w3, hd_b3, nullptr, (float*)d_out, NN, 4, 512, 0);
}

// round 2
// speedup vs baseline: 3.5200x; 3.5200x over previous
#include <cuda_runtime.h>
#include <stdint.h>

#define NN 20000
#define NE 320000

// ---------------- static scratch ----------------
__device__ float g_bufA[(size_t)NN * 1024];
__device__ float g_bufB[(size_t)NN * 1024];
__device__ float g_bufC[(size_t)NN * 1024];
__device__ float g_cnt[NN];
__device__ float g_inv[NN];
__device__ int   g_src[NE];
__device__ int   g_dst[NE];
__device__ float2 g_rel[NE];
__device__ int   g_idx64;

// ---------------- setup kernels ----------------
__global__ void detect_idx_kernel(const int* e) {
    if (threadIdx.x == 0 && blockIdx.x == 0) {
        int is64 = 1;
        for (int k = 0; k < 128; k++) {
            if (e[2 * k + 1] != 0) { is64 = 0; break; }
        }
        g_idx64 = is64;
    }
}

__global__ void zero4_kernel(float4* p, int n4) {
    int i = blockIdx.x * blockDim.x + threadIdx.x;
    if (i < n4) p[i] = make_float4(0.f, 0.f, 0.f, 0.f);
}

__global__ void prep_edges_kernel(const void* eidx, const float* __restrict__ pos) {
    int e = blockIdx.x * blockDim.x + threadIdx.x;
    if (e >= NE) return;
    int s, d;
    if (g_idx64) {
        s = (int)((const long long*)eidx)[e];
        d = (int)((const long long*)eidx)[(long long)NE + e];
    } else {
        s = ((const int*)eidx)[e];
        d = ((const int*)eidx)[NE + e];
    }
    g_src[e] = s;
    g_dst[e] = d;
    g_rel[e] = make_float2(pos[2 * s] - pos[2 * d], pos[2 * s + 1] - pos[2 * d + 1]);
    atomicAdd(&g_cnt[d], 1.f);
}

__global__ void make_inv_kernel() {
    int i = blockIdx.x * blockDim.x + threadIdx.x;
    if (i < NN) {
        float c = g_cnt[i];
        g_inv[i] = (c > 0.f) ? (1.f / c) : 0.f;
    }
}

// ---------------- TF32 tensor-core GEMM ----------------
// C = act( rowscale[r]*(A@B) + bias ), A: MxK row-major, B: KxN row-major.
// CTA tile 128x128, BK=32, 256 threads (8 warps as 2x4, warp tile 64x32),
// double-buffered cp.async, mma.sync m16n8k8 tf32.
#define BM 128
#define BN 128
#define BKD 32
#define APITCH 36
#define BPITCH 136
#define ASTAGE (BM * APITCH)            // 4608 floats
#define BSTAGE (BKD * BPITCH)           // 4352 floats
#define SMEM_BYTES ((2 * ASTAGE + 2 * BSTAGE) * 4)  // 71680

__device__ __forceinline__ uint32_t f2tf(float x) {
    uint32_t r;
    asm("cvt.rna.tf32.f32 %0, %1;" : "=r"(r) : "f"(x));
    return r;
}

__device__ __forceinline__ void cp16(uint32_t dst, const float* src, bool v) {
    if (v)
        asm volatile("cp.async.cg.shared.global [%0], [%1], 16;" :: "r"(dst), "l"(src));
    else
        asm volatile("cp.async.cg.shared.global [%0], [%1], 16, 0;" :: "r"(dst), "l"(src));
}

__global__ void __launch_bounds__(256)
mma_gemm_kernel(const float* __restrict__ A, const float* __restrict__ B,
                const float* __restrict__ bias, const float* __restrict__ rowscale,
                float* __restrict__ C, int M, int N, int K, int doRelu)
{
    extern __shared__ float sm[];
    float* As = sm;                 // [2][BM][APITCH]
    float* Bs = sm + 2 * ASTAGE;    // [2][BKD][BPITCH]

    const int tid = threadIdx.x;
    const int rowBase = blockIdx.y * BM;
    const int colBase = blockIdx.x * BN;

    const int wid = tid >> 5, lane = tid & 31;
    const int wr = wid >> 2, wc = wid & 3;   // 2 x 4 warps
    const int mW = wr * 64, nW = wc * 32;
    const int g = lane >> 2, t = lane & 3;

    uint32_t asBase = (uint32_t)__cvta_generic_to_shared(As);
    uint32_t bsBase = (uint32_t)__cvta_generic_to_shared(Bs);

    auto prefetch = [&](int k0, int buf) {
#pragma unroll
        for (int i = 0; i < 4; i++) {
            int idx = tid + 256 * i;
            int r = idx >> 3, c4 = (idx & 7) << 2;
            bool v = (rowBase + r < M) && (k0 + c4 < K);
            const float* src = v ? (A + (size_t)(rowBase + r) * K + k0 + c4) : A;
            cp16(asBase + (uint32_t)(buf * ASTAGE + r * APITCH + c4) * 4, src, v);
        }
#pragma unroll
        for (int i = 0; i < 4; i++) {
            int idx = tid + 256 * i;
            int r = idx >> 5, c4 = (idx & 31) << 2;
            bool v = (k0 + r < K);
            const float* src = v ? (B + (size_t)(k0 + r) * N + colBase + c4) : B;
            cp16(bsBase + (uint32_t)(buf * BSTAGE + r * BPITCH + c4) * 4, src, v);
        }
    };

    float acc[4][4][4];
#pragma unroll
    for (int a = 0; a < 4; a++)
#pragma unroll
        for (int b = 0; b < 4; b++)
#pragma unroll
            for (int c = 0; c < 4; c++) acc[a][b][c] = 0.f;

    const int nk = (K + BKD - 1) / BKD;
    prefetch(0, 0);
    asm volatile("cp.async.commit_group;");

    for (int s = 0; s < nk; s++) {
        const int buf = s & 1;
        if (s + 1 < nk) {
            prefetch((s + 1) * BKD, buf ^ 1);
            asm volatile("cp.async.commit_group;");
            asm volatile("cp.async.wait_group 1;");
        } else {
            asm volatile("cp.async.wait_group 0;");
        }
        __syncthreads();

        const float* As_ = As + buf * ASTAGE;
        const float* Bs_ = Bs + buf * BSTAGE;

#pragma unroll
        for (int kk = 0; kk < 4; kk++) {
            uint32_t af[4][4];
#pragma unroll
            for (int mt = 0; mt < 4; mt++) {
                const float* ap = As_ + (mW + mt * 16 + g) * APITCH + kk * 8 + t;
                af[mt][0] = f2tf(ap[0]);
                af[mt][1] = f2tf(ap[8 * APITCH]);
                af[mt][2] = f2tf(ap[4]);
                af[mt][3] = f2tf(ap[8 * APITCH + 4]);
            }
            uint32_t bf[4][2];
#pragma unroll
            for (int nt = 0; nt < 4; nt++) {
                const float* bp = Bs_ + (kk * 8 + t) * BPITCH + nW + nt * 8 + g;
                bf[nt][0] = f2tf(bp[0]);
                bf[nt][1] = f2tf(bp[4 * BPITCH]);
            }
#pragma unroll
            for (int mt = 0; mt < 4; mt++)
#pragma unroll
                for (int nt = 0; nt < 4; nt++)
                    asm volatile(
                        "mma.sync.aligned.m16n8k8.row.col.f32.tf32.tf32.f32 "
                        "{%0,%1,%2,%3}, {%4,%5,%6,%7}, {%8,%9}, {%0,%1,%2,%3};"
                        : "+f"(acc[mt][nt][0]), "+f"(acc[mt][nt][1]),
                          "+f"(acc[mt][nt][2]), "+f"(acc[mt][nt][3])
                        : "r"(af[mt][0]), "r"(af[mt][1]), "r"(af[mt][2]), "r"(af[mt][3]),
                          "r"(bf[nt][0]), "r"(bf[nt][1]));
        }
        __syncthreads();
    }

    // epilogue: c0=(g,2t) c1=(g,2t+1) c2=(g+8,2t) c3=(g+8,2t+1)
#pragma unroll
    for (int mt = 0; mt < 4; mt++) {
        const int r0 = rowBase + mW + mt * 16 + g;
#pragma unroll
        for (int half = 0; half < 2; half++) {
            const int r = r0 + half * 8;
            if (r >= M) continue;
            const float rs = rowscale ? rowscale[r] : 1.f;
            const bool masked = (rowscale != nullptr) && (rs == 0.f);
#pragma unroll
            for (int nt = 0; nt < 4; nt++) {
                const int c = colBase + nW + nt * 8 + 2 * t;
                float v0 = acc[mt][nt][half * 2 + 0] * rs + bias[c];
                float v1 = acc[mt][nt][half * 2 + 1] * rs + bias[c + 1];
                if (doRelu) { v0 = fmaxf(v0, 0.f); v1 = fmaxf(v1, 0.f); }
                if (masked) { v0 = 0.f; v1 = 0.f; }
                *(float2*)(C + (size_t)r * N + c) = make_float2(v0, v1);
            }
        }
    }
}

// ---------------- edge scatter ----------------
__global__ void edge_scatter_kernel(const float* __restrict__ t,
                                    const float* __restrict__ wpos,
                                    float* __restrict__ s, int laneShift)
{
    const long long gid = (long long)blockIdx.x * blockDim.x + threadIdx.x;
    const int lanes = 1 << laneShift;
    const long long e = gid >> laneShift;
    if (e >= NE) return;
    const int H = lanes * 4;
    const int c4 = (int)(gid & (lanes - 1)) << 2;

    const int src = g_src[e];
    const int dst = g_dst[e];
    const float2 d = g_rel[e];

    const float4 tv = *(const float4*)(t + (size_t)src * H + c4);
    const float4 wx = *(const float4*)(wpos + c4);
    const float4 wy = *(const float4*)(wpos + H + c4);

    float4 r;
    r.x = fmaxf(fmaf(d.x, wx.x, fmaf(d.y, wy.x, tv.x)), 0.f);
    r.y = fmaxf(fmaf(d.x, wx.y, fmaf(d.y, wy.y, tv.y)), 0.f);
    r.z = fmaxf(fmaf(d.x, wx.z, fmaf(d.y, wy.z, tv.z)), 0.f);
    r.w = fmaxf(fmaf(d.x, wx.w, fmaf(d.y, wy.w, tv.w)), 0.f);

    float* sp = s + (size_t)dst * H + c4;
    asm volatile("red.global.add.v4.f32 [%0], {%1, %2, %3, %4};"
                 :: "l"(sp), "f"(r.x), "f"(r.y), "f"(r.z), "f"(r.w) : "memory");
}

// ---------------- final head GEMM (N=4): one warp per row ----------------
__global__ void headN4_kernel(const float* __restrict__ A, const float* __restrict__ W,
                              const float* __restrict__ b, float* __restrict__ out)
{
    const int warp = (blockIdx.x * blockDim.x + threadIdx.x) >> 5;
    const int lane = threadIdx.x & 31;
    if (warp >= NN) return;
    const float* ar = A + (size_t)warp * 512;
    float s0 = 0.f, s1 = 0.f, s2 = 0.f, s3 = 0.f;
    for (int k = lane; k < 512; k += 32) {
        const float a = ar[k];
        const float4 w = *(const float4*)(W + k * 4);
        s0 = fmaf(a, w.x, s0); s1 = fmaf(a, w.y, s1);
        s2 = fmaf(a, w.z, s2); s3 = fmaf(a, w.w, s3);
    }
#pragma unroll
    for (int o = 16; o; o >>= 1) {
        s0 += __shfl_down_sync(0xFFFFFFFFu, s0, o);
        s1 += __shfl_down_sync(0xFFFFFFFFu, s1, o);
        s2 += __shfl_down_sync(0xFFFFFFFFu, s2, o);
        s3 += __shfl_down_sync(0xFFFFFFFFu, s3, o);
    }
    if (lane == 0)
        *(float4*)(out + (size_t)warp * 4) =
            make_float4(s0 + b[0], s1 + b[1], s2 + b[2], s3 + b[3]);
}

// ---------------- host helpers ----------------
static inline void run_mma(const float* A, const float* B, const float* bias,
                           const float* rowscale, float* C, int M, int N, int K, int doRelu)
{
    dim3 grid(N / 128, (M + 127) / 128);
    mma_gemm_kernel<<<grid, 256, SMEM_BYTES>>>(A, B, bias, rowscale, C, M, N, K, doRelu);
}

static inline void run_zero(float* p, long long n)
{
    long long n4 = n >> 2;
    zero4_kernel<<<(unsigned)((n4 + 255) / 256), 256>>>((float4*)p, (int)n4);
}

static inline void run_edge(const float* t, const float* wpos, float* s, int laneShift)
{
    const long long total = (long long)NE << laneShift;
    edge_scatter_kernel<<<(unsigned)((total + 255) / 256), 256>>>(t, wpos, s, laneShift);
}

extern "C" void kernel_launch(void* const* d_in, const int* in_sizes, int n_in,
                              void* d_out, int out_size)
{
    const float* h    = (const float*)d_in[0];
    const float* pos  = (const float*)d_in[1];
    const void*  eidx = d_in[2];

    const float* l1_w1 = (const float*)d_in[3];
    const float* l1_b1 = (const float*)d_in[4];
    const float* l1_w2 = (const float*)d_in[5];
    const float* l1_b2 = (const float*)d_in[6];
    const float* l2_w1 = (const float*)d_in[7];
    const float* l2_b1 = (const float*)d_in[8];
    const float* l2_w2 = (const float*)d_in[9];
    const float* l2_b2 = (const float*)d_in[10];
    const float* l3_w1 = (const float*)d_in[11];
    const float* l3_b1 = (const float*)d_in[12];
    const float* l3_w2 = (const float*)d_in[13];
    const float* l3_b2 = (const float*)d_in[14];
    const float* l4_w1 = (const float*)d_in[15];
    const float* l4_b1 = (const float*)d_in[16];
    const float* l4_w2 = (const float*)d_in[17];
    const float* l4_b2 = (const float*)d_in[18];
    const float* hd_w1 = (const float*)d_in[19];
    const float* hd_b1 = (const float*)d_in[20];
    const float* hd_w2 = (const float*)d_in[21];
    const float* hd_b2 = (const float*)d_in[22];
    const float* hd_w3 = (const float*)d_in[23];
    const float* hd_b3 = (const float*)d_in[24];

    float *bufA, *bufB, *bufC, *cnt, *inv;
    cudaGetSymbolAddress((void**)&bufA, g_bufA);
    cudaGetSymbolAddress((void**)&bufB, g_bufB);
    cudaGetSymbolAddress((void**)&bufC, g_bufC);
    cudaGetSymbolAddress((void**)&cnt, g_cnt);
    cudaGetSymbolAddress((void**)&inv, g_inv);

    cudaFuncSetAttribute(mma_gemm_kernel,
                         cudaFuncAttributeMaxDynamicSharedMemorySize, SMEM_BYTES);

    // --- setup ---
    detect_idx_kernel<<<1, 32>>>((const int*)d_in[2]);
    run_zero(cnt, NN);
    prep_edges_kernel<<<(NE + 255) / 256, 256>>>(eidx, pos);
    make_inv_kernel<<<(NN + 255) / 256, 256>>>();

    // --- layer 1: 16 -> 128 -> 128 ---
    run_mma(h, l1_w1, l1_b1, nullptr, bufB, NN, 128, 16, 0);
    run_zero(bufC, (long long)NN * 128);
    run_edge(bufB, l1_w1 + (size_t)16 * 128, bufC, 5);
    run_mma(bufC, l1_w2, l1_b2, inv, bufA, NN, 128, 128, 1);

    // --- layer 2: 128 -> 256 -> 256 ---
    run_mma(bufA, l2_w1, l2_b1, nullptr, bufB, NN, 256, 128, 0);
    run_zero(bufC, (long long)NN * 256);
    run_edge(bufB, l2_w1 + (size_t)128 * 256, bufC, 6);
    run_mma(bufC, l2_w2, l2_b2, inv, bufA, NN, 256, 256, 1);

    // --- layer 3: 256 -> 1024 -> 1024 ---
    run_mma(bufA, l3_w1, l3_b1, nullptr, bufB, NN, 1024, 256, 0);
    run_zero(bufC, (long long)NN * 1024);
    run_edge(bufB, l3_w1 + (size_t)256 * 1024, bufC, 8);
    run_mma(bufC, l3_w2, l3_b2, inv, bufA, NN, 1024, 1024, 1);

    // --- layer 4: 1024 -> 1024 -> 1024 ---
    run_mma(bufA, l4_w1, l4_b1, nullptr, bufB, NN, 1024, 1024, 0);
    run_zero(bufC, (long long)NN * 1024);
    run_edge(bufB, l4_w1 + (size_t)1024 * 1024, bufC, 8);
    run_mma(bufC, l4_w2, l4_b2, inv, bufA, NN, 1024, 1024, 1);

    // --- head MLP ---
    run_mma(bufA, hd_w1, hd_b1, nullptr, bufB, NN, 1024, 1024, 1);
    run_mma(bufB, hd_w2, hd_b2, nullptr, bufC, NN, 512, 1024, 1);
    headN4_kernel<<<(NN * 32 + 255) / 256, 256>>>(bufC, hd_w3, hd_b3, (float*)d_out);
}

// round 3
// speedup vs baseline: 4.6271x; 1.3145x over previous
#include <cuda_runtime.h>
#include <stdint.h>

#define NN 20000
#define NE 320000

// ---------------- static scratch ----------------
__device__ float g_bufA[(size_t)NN * 1024];
__device__ float g_bufB[(size_t)NN * 1024];
__device__ float g_bufC[(size_t)NN * 1024];
__device__ float g_inv[NN];
__device__ int   g_cnti[NN];
__device__ int   g_fill[NN];
__device__ int   g_rowptr[NN + 1];
__device__ int   g_esrc[NE];
__device__ float2 g_erel[NE];
__device__ int   g_idx64;

// ---------------- setup kernels ----------------
__global__ void detect_idx_kernel(const int* e) {
    if (threadIdx.x == 0 && blockIdx.x == 0) {
        int is64 = 1;
        for (int k = 0; k < 128; k++) {
            if (e[2 * k + 1] != 0) { is64 = 0; break; }
        }
        g_idx64 = is64;
    }
}

__global__ void zero2_int_kernel() {
    int i = blockIdx.x * blockDim.x + threadIdx.x;
    if (i < NN) { g_cnti[i] = 0; g_fill[i] = 0; }
}

__global__ void count_kernel(const void* eidx) {
    int e = blockIdx.x * blockDim.x + threadIdx.x;
    if (e >= NE) return;
    int d;
    if (g_idx64) d = (int)((const long long*)eidx)[(long long)NE + e];
    else         d = ((const int*)eidx)[NE + e];
    atomicAdd(&g_cnti[d], 1);
}

// single-block exclusive scan over g_cnti -> g_rowptr
__global__ void scan_kernel() {
    __shared__ int part[1024];
    const int t = threadIdx.x;
    const int CH = 20;  // 1024*20 >= NN
    const int base = t * CH;
    int s = 0;
    for (int i = 0; i < CH; i++) {
        int idx = base + i;
        if (idx < NN) s += g_cnti[idx];
    }
    part[t] = s;
    __syncthreads();
    for (int off = 1; off < 1024; off <<= 1) {
        int v = 0;
        if (t >= off) v = part[t - off];
        __syncthreads();
        part[t] += v;
        __syncthreads();
    }
    int run = (t == 0) ? 0 : part[t - 1];
    for (int i = 0; i < CH; i++) {
        int idx = base + i;
        if (idx < NN) { g_rowptr[idx] = run; run += g_cnti[idx]; }
    }
    if (t == 1023) g_rowptr[NN] = part[1023];
}

__global__ void fill_kernel(const void* eidx, const float* __restrict__ pos) {
    int e = blockIdx.x * blockDim.x + threadIdx.x;
    if (e >= NE) return;
    int s, d;
    if (g_idx64) {
        s = (int)((const long long*)eidx)[e];
        d = (int)((const long long*)eidx)[(long long)NE + e];
    } else {
        s = ((const int*)eidx)[e];
        d = ((const int*)eidx)[NE + e];
    }
    int p = g_rowptr[d] + atomicAdd(&g_fill[d], 1);
    g_esrc[p] = s;
    g_erel[p] = make_float2(pos[2 * s] - pos[2 * d], pos[2 * s + 1] - pos[2 * d + 1]);
}

__global__ void make_inv_kernel() {
    int i = blockIdx.x * blockDim.x + threadIdx.x;
    if (i < NN) {
        int c = g_rowptr[i + 1] - g_rowptr[i];
        g_inv[i] = (c > 0) ? (1.f / (float)c) : 0.f;
    }
}

// ---------------- TF32 tensor-core GEMM ----------------
// C = act( rowscale[r]*(A@B) + bias ), A: MxK row-major, B: KxN row-major.
// CTA tile 128x128, BK=32, 256 threads (2x4 warps, warp tile 64x32),
// double-buffered cp.async, mma.sync m16n8k8 tf32 (HW truncation, no cvt).
#define BM 128
#define BN 128
#define BKD 32
#define APITCH 36
#define BPITCH 136
#define ASTAGE (BM * APITCH)
#define BSTAGE (BKD * BPITCH)
#define SMEM_BYTES ((2 * ASTAGE + 2 * BSTAGE) * 4)

__device__ __forceinline__ void cp16(uint32_t dst, const float* src, bool v) {
    if (v)
        asm volatile("cp.async.cg.shared.global [%0], [%1], 16;" :: "r"(dst), "l"(src));
    else
        asm volatile("cp.async.cg.shared.global [%0], [%1], 16, 0;" :: "r"(dst), "l"(src));
}

__global__ void __launch_bounds__(256)
mma_gemm_kernel(const float* __restrict__ A, const float* __restrict__ B,
                const float* __restrict__ bias, const float* __restrict__ rowscale,
                float* __restrict__ C, int M, int N, int K, int doRelu)
{
    extern __shared__ float sm[];
    float* As = sm;
    float* Bs = sm + 2 * ASTAGE;

    const int tid = threadIdx.x;
    const int rowBase = blockIdx.y * BM;
    const int colBase = blockIdx.x * BN;

    const int wid = tid >> 5, lane = tid & 31;
    const int wr = wid >> 2, wc = wid & 3;
    const int mW = wr * 64, nW = wc * 32;
    const int g = lane >> 2, t = lane & 3;

    uint32_t asBase = (uint32_t)__cvta_generic_to_shared(As);
    uint32_t bsBase = (uint32_t)__cvta_generic_to_shared(Bs);

    auto prefetch = [&](int k0, int buf) {
#pragma unroll
        for (int i = 0; i < 4; i++) {
            int idx = tid + 256 * i;
            int r = idx >> 3, c4 = (idx & 7) << 2;
            bool v = (rowBase + r < M) && (k0 + c4 < K);
            const float* src = v ? (A + (size_t)(rowBase + r) * K + k0 + c4) : A;
            cp16(asBase + (uint32_t)(buf * ASTAGE + r * APITCH + c4) * 4, src, v);
        }
#pragma unroll
        for (int i = 0; i < 4; i++) {
            int idx = tid + 256 * i;
            int r = idx >> 5, c4 = (idx & 31) << 2;
            bool v = (k0 + r < K);
            const float* src = v ? (B + (size_t)(k0 + r) * N + colBase + c4) : B;
            cp16(bsBase + (uint32_t)(buf * BSTAGE + r * BPITCH + c4) * 4, src, v);
        }
    };

    float acc[4][4][4];
#pragma unroll
    for (int a = 0; a < 4; a++)
#pragma unroll
        for (int b = 0; b < 4; b++)
#pragma unroll
            for (int c = 0; c < 4; c++) acc[a][b][c] = 0.f;

    const int nk = (K + BKD - 1) / BKD;
    prefetch(0, 0);
    asm volatile("cp.async.commit_group;");

    for (int s = 0; s < nk; s++) {
        const int buf = s & 1;
        if (s + 1 < nk) {
            prefetch((s + 1) * BKD, buf ^ 1);
            asm volatile("cp.async.commit_group;");
            asm volatile("cp.async.wait_group 1;");
        } else {
            asm volatile("cp.async.wait_group 0;");
        }
        __syncthreads();

        const float* As_ = As + buf * ASTAGE;
        const float* Bs_ = Bs + buf * BSTAGE;

#pragma unroll
        for (int kk = 0; kk < 4; kk++) {
            uint32_t af[4][4];
#pragma unroll
            for (int mt = 0; mt < 4; mt++) {
                const float* ap = As_ + (mW + mt * 16 + g) * APITCH + kk * 8 + t;
                af[mt][0] = __float_as_uint(ap[0]);
                af[mt][1] = __float_as_uint(ap[8 * APITCH]);
                af[mt][2] = __float_as_uint(ap[4]);
                af[mt][3] = __float_as_uint(ap[8 * APITCH + 4]);
            }
            uint32_t bf[4][2];
#pragma unroll
            for (int nt = 0; nt < 4; nt++) {
                const float* bp = Bs_ + (kk * 8 + t) * BPITCH + nW + nt * 8 + g;
                bf[nt][0] = __float_as_uint(bp[0]);
                bf[nt][1] = __float_as_uint(bp[4 * BPITCH]);
            }
#pragma unroll
            for (int mt = 0; mt < 4; mt++)
#pragma unroll
                for (int nt = 0; nt < 4; nt++)
                    asm volatile(
                        "mma.sync.aligned.m16n8k8.row.col.f32.tf32.tf32.f32 "
                        "{%0,%1,%2,%3}, {%4,%5,%6,%7}, {%8,%9}, {%0,%1,%2,%3};"
                        : "+f"(acc[mt][nt][0]), "+f"(acc[mt][nt][1]),
                          "+f"(acc[mt][nt][2]), "+f"(acc[mt][nt][3])
                        : "r"(af[mt][0]), "r"(af[mt][1]), "r"(af[mt][2]), "r"(af[mt][3]),
                          "r"(bf[nt][0]), "r"(bf[nt][1]));
        }
        __syncthreads();
    }

#pragma unroll
    for (int mt = 0; mt < 4; mt++) {
        const int r0 = rowBase + mW + mt * 16 + g;
#pragma unroll
        for (int half = 0; half < 2; half++) {
            const int r = r0 + half * 8;
            if (r >= M) continue;
            const float rs = rowscale ? rowscale[r] : 1.f;
            const bool masked = (rowscale != nullptr) && (rs == 0.f);
#pragma unroll
            for (int nt = 0; nt < 4; nt++) {
                const int c = colBase + nW + nt * 8 + 2 * t;
                float v0 = acc[mt][nt][half * 2 + 0] * rs + bias[c];
                float v1 = acc[mt][nt][half * 2 + 1] * rs + bias[c + 1];
                if (doRelu) { v0 = fmaxf(v0, 0.f); v1 = fmaxf(v1, 0.f); }
                if (masked) { v0 = 0.f; v1 = 0.f; }
                *(float2*)(C + (size_t)r * N + c) = make_float2(v0, v1);
            }
        }
    }
}

// ---------------- CSR gather-aggregate ----------------
// One warp per (node, 128-col block). s[node] = sum_e relu(t[src_e] + dx*wx + dy*wy).
// No atomics, no zero-fill: plain register accumulation + one STG.
__global__ void aggregate_kernel(const float* __restrict__ t,
                                 const float* __restrict__ wpos,
                                 float* __restrict__ out, int H, int cbShift)
{
    const int warpGlobal = (blockIdx.x * blockDim.x + threadIdx.x) >> 5;
    const int lane = threadIdx.x & 31;
    const int node = warpGlobal >> cbShift;
    if (node >= NN) return;
    const int cb = warpGlobal & ((1 << cbShift) - 1);
    const int col = cb * 128 + lane * 4;

    const float4 wx = *(const float4*)(wpos + col);
    const float4 wy = *(const float4*)(wpos + H + col);

    const int beg = g_rowptr[node];
    const int end = g_rowptr[node + 1];

    float4 acc = make_float4(0.f, 0.f, 0.f, 0.f);

    for (int b = beg; b < end; b += 32) {
        const int n = min(32, end - b);
        int sj = 0;
        float rxj = 0.f, ryj = 0.f;
        if (b + lane < end) {
            sj = g_esrc[b + lane];
            float2 rr = g_erel[b + lane];
            rxj = rr.x; ryj = rr.y;
        }
#pragma unroll 4
        for (int j = 0; j < n; j++) {
            const int s = __shfl_sync(0xFFFFFFFFu, sj, j);
            const float rx = __shfl_sync(0xFFFFFFFFu, rxj, j);
            const float ry = __shfl_sync(0xFFFFFFFFu, ryj, j);
            const float4 tv = *(const float4*)(t + (size_t)s * H + col);
            acc.x += fmaxf(fmaf(rx, wx.x, fmaf(ry, wy.x, tv.x)), 0.f);
            acc.y += fmaxf(fmaf(rx, wx.y, fmaf(ry, wy.y, tv.y)), 0.f);
            acc.z += fmaxf(fmaf(rx, wx.z, fmaf(ry, wy.z, tv.z)), 0.f);
            acc.w += fmaxf(fmaf(rx, wx.w, fmaf(ry, wy.w, tv.w)), 0.f);
        }
    }
    *(float4*)(out + (size_t)node * H + col) = acc;
}

// ---------------- final head GEMM (N=4) ----------------
__global__ void headN4_kernel(const float* __restrict__ A, const float* __restrict__ W,
                              const float* __restrict__ b, float* __restrict__ out)
{
    const int warp = (blockIdx.x * blockDim.x + threadIdx.x) >> 5;
    const int lane = threadIdx.x & 31;
    if (warp >= NN) return;
    const float* ar = A + (size_t)warp * 512;
    float s0 = 0.f, s1 = 0.f, s2 = 0.f, s3 = 0.f;
    for (int k = lane; k < 512; k += 32) {
        const float a = ar[k];
        const float4 w = *(const float4*)(W + k * 4);
        s0 = fmaf(a, w.x, s0); s1 = fmaf(a, w.y, s1);
        s2 = fmaf(a, w.z, s2); s3 = fmaf(a, w.w, s3);
    }
#pragma unroll
    for (int o = 16; o; o >>= 1) {
        s0 += __shfl_down_sync(0xFFFFFFFFu, s0, o);
        s1 += __shfl_down_sync(0xFFFFFFFFu, s1, o);
        s2 += __shfl_down_sync(0xFFFFFFFFu, s2, o);
        s3 += __shfl_down_sync(0xFFFFFFFFu, s3, o);
    }
    if (lane == 0)
        *(float4*)(out + (size_t)warp * 4) =
            make_float4(s0 + b[0], s1 + b[1], s2 + b[2], s3 + b[3]);
}

// ---------------- host helpers ----------------
static inline void run_mma(const float* A, const float* B, const float* bias,
                           const float* rowscale, float* C, int M, int N, int K, int doRelu)
{
    dim3 grid(N / 128, (M + 127) / 128);
    mma_gemm_kernel<<<grid, 256, SMEM_BYTES>>>(A, B, bias, rowscale, C, M, N, K, doRelu);
}

static inline void run_agg(const float* t, const float* wpos, float* s, int H, int cbShift)
{
    const long long threads = ((long long)NN << cbShift) * 32;
    aggregate_kernel<<<(unsigned)((threads + 255) / 256), 256>>>(t, wpos, s, H, cbShift);
}

extern "C" void kernel_launch(void* const* d_in, const int* in_sizes, int n_in,
                              void* d_out, int out_size)
{
    const float* h    = (const float*)d_in[0];
    const float* pos  = (const float*)d_in[1];
    const void*  eidx = d_in[2];

    const float* l1_w1 = (const float*)d_in[3];
    const float* l1_b1 = (const float*)d_in[4];
    const float* l1_w2 = (const float*)d_in[5];
    const float* l1_b2 = (const float*)d_in[6];
    const float* l2_w1 = (const float*)d_in[7];
    const float* l2_b1 = (const float*)d_in[8];
    const float* l2_w2 = (const float*)d_in[9];
    const float* l2_b2 = (const float*)d_in[10];
    const float* l3_w1 = (const float*)d_in[11];
    const float* l3_b1 = (const float*)d_in[12];
    const float* l3_w2 = (const float*)d_in[13];
    const float* l3_b2 = (const float*)d_in[14];
    const float* l4_w1 = (const float*)d_in[15];
    const float* l4_b1 = (const float*)d_in[16];
    const float* l4_w2 = (const float*)d_in[17];
    const float* l4_b2 = (const float*)d_in[18];
    const float* hd_w1 = (const float*)d_in[19];
    const float* hd_b1 = (const float*)d_in[20];
    const float* hd_w2 = (const float*)d_in[21];
    const float* hd_b2 = (const float*)d_in[22];
    const float* hd_w3 = (const float*)d_in[23];
    const float* hd_b3 = (const float*)d_in[24];

    float *bufA, *bufB, *bufC, *inv;
    cudaGetSymbolAddress((void**)&bufA, g_bufA);
    cudaGetSymbolAddress((void**)&bufB, g_bufB);
    cudaGetSymbolAddress((void**)&bufC, g_bufC);
    cudaGetSymbolAddress((void**)&inv, g_inv);

    cudaFuncSetAttribute(mma_gemm_kernel,
                         cudaFuncAttributeMaxDynamicSharedMemorySize, SMEM_BYTES);

    // --- setup: CSR build ---
    detect_idx_kernel<<<1, 32>>>((const int*)d_in[2]);
    zero2_int_kernel<<<(NN + 255) / 256, 256>>>();
    count_kernel<<<(NE + 255) / 256, 256>>>(eidx);
    scan_kernel<<<1, 1024>>>();
    fill_kernel<<<(NE + 255) / 256, 256>>>(eidx, pos);
    make_inv_kernel<<<(NN + 255) / 256, 256>>>();

    // --- layer 1: 16 -> 128 -> 128 ---
    run_mma(h, l1_w1, l1_b1, nullptr, bufB, NN, 128, 16, 0);
    run_agg(bufB, l1_w1 + (size_t)16 * 128, bufC, 128, 0);
    run_mma(bufC, l1_w2, l1_b2, inv, bufA, NN, 128, 128, 1);

    // --- layer 2: 128 -> 256 -> 256 ---
    run_mma(bufA, l2_w1, l2_b1, nullptr, bufB, NN, 256, 128, 0);
    run_agg(bufB, l2_w1 + (size_t)128 * 256, bufC, 256, 1);
    run_mma(bufC, l2_w2, l2_b2, inv, bufA, NN, 256, 256, 1);

    // --- layer 3: 256 -> 1024 -> 1024 ---
    run_mma(bufA, l3_w1, l3_b1, nullptr, bufB, NN, 1024, 256, 0);
    run_agg(bufB, l3_w1 + (size_t)256 * 1024, bufC, 1024, 3);
    run_mma(bufC, l3_w2, l3_b2, inv, bufA, NN, 1024, 1024, 1);

    // --- layer 4: 1024 -> 1024 -> 1024 ---
    run_mma(bufA, l4_w1, l4_b1, nullptr, bufB, NN, 1024, 1024, 0);
    run_agg(bufB, l4_w1 + (size_t)1024 * 1024, bufC, 1024, 3);
    run_mma(bufC, l4_w2, l4_b2, inv, bufA, NN, 1024, 1024, 1);

    // --- head MLP ---
    run_mma(bufA, hd_w1, hd_b1, nullptr, bufB, NN, 1024, 1024, 1);
    run_mma(bufB, hd_w2, hd_b2, nullptr, bufC, NN, 512, 1024, 1);
    headN4_kernel<<<(NN * 32 + 255) / 256, 256>>>(bufC, hd_w3, hd_b3, (float*)d_out);
}